// round 4
// baseline (speedup 1.0000x reference)
#include <cuda_runtime.h>
#include <cuda_bf16.h>

// B=128 matrices of N=512. For each superdiagonal k (offset k+1, k<510),
// sample variance over its L=511-k elements, scaled = sqrt(var)*L/5,
// loss[b] = mean_k scaled. Output: loss twice (2*128 floats).
//
// Two-kernel plan:
//  K1 (accumulate): grid (128 batches x 8 row-slices), 128 threads.
//     Slice s handles rows p ≡ s (mod 8)  =>  p mod 4 is FIXED per block,
//     so float4 loads at diag offset k ≡ k_start(s) (mod 4) are 16B-aligned.
//     Each lane owns 4 consecutive diagonals; groups of 128 diagonals are
//     paired (g, 3-g) across warps for perfect balance (~40 LDG.128/warp).
//     Per-lane load predicate => traffic is exact (no overshoot).
//     The <=3 "head" diagonals k < k_start get a lane-parallel scalar pass.
//     Partials merged via shared atomics, written to __device__ scratch
//     (every slot written each launch => no zeroing, deterministic layout).
//  K2 (finalize): grid 128, 512 threads. Sums 8 slice-partials per k,
//     computes scaled, block-reduces, writes both output copies.

constexpr int BATCH = 128;
constexpr int NMAT  = 512;
constexpr int S     = 8;     // row slices per batch
constexpr int KP    = 520;   // padded per-k slots (max written index 514)

__device__ float g_psum[S][BATCH][KP];
__device__ float g_psq [S][BATCH][KP];

__global__ __launch_bounds__(128)
void accum_kernel(const float* __restrict__ ssmap) {
    __shared__ float s_sum[KP];
    __shared__ float s_sq [KP];

    const int b   = blockIdx.x;
    const int s   = blockIdx.y;
    const int tid = threadIdx.x;
    const int w    = tid >> 5;
    const int lane = tid & 31;
    const int pairIdx = w & 1;   // which group-pair: {0,3} or {1,2}
    const int j       = w >> 1;  // row sub-split within slice (0/1)
    const int k_start = (3 - (s & 3)) & 3;   // aligned diag offset for this slice
    const float* base = ssmap + (size_t)b * (NMAT * NMAT);

    for (int i = tid; i < KP; i += 128) { s_sum[i] = 0.0f; s_sq[i] = 0.0f; }
    __syncthreads();

    #pragma unroll
    for (int g2 = 0; g2 < 2; ++g2) {
        const int g      = pairIdx ? (g2 ? 2 : 1) : (g2 ? 3 : 0);
        const int kgb    = k_start + 128 * g;
        const int k_base = kgb + 4 * lane;       // this lane's first diagonal
        const int maxL   = 511 - kgb;            // longest diagonal in group
        const int lim    = 511 - k_base;         // lane load bound (may be <=0)

        float a0 = 0.f, a1 = 0.f, a2 = 0.f, a3 = 0.f;
        float q0 = 0.f, q1 = 0.f, q2 = 0.f, q3 = 0.f;

        #pragma unroll 4
        for (int p = s + 8 * j; p < maxL; p += 16) {
            if (p < lim) {   // predicated load: no traffic for dead lanes
                const float4 v =
                    __ldcs((const float4*)(base + (size_t)513 * p + (k_base + 1)));
                a0 += v.x; q0 = fmaf(v.x, v.x, q0);
                if (p < lim - 1) { a1 += v.y; q1 = fmaf(v.y, v.y, q1); }
                if (p < lim - 2) { a2 += v.z; q2 = fmaf(v.z, v.z, q2); }
                if (p < lim - 3) { a3 += v.w; q3 = fmaf(v.w, v.w, q3); }
            }
        }
        if (lim > 0) {
            atomicAdd(&s_sum[k_base + 0], a0); atomicAdd(&s_sq[k_base + 0], q0);
            atomicAdd(&s_sum[k_base + 1], a1); atomicAdd(&s_sq[k_base + 1], q1);
            atomicAdd(&s_sum[k_base + 2], a2); atomicAdd(&s_sq[k_base + 2], q2);
            atomicAdd(&s_sum[k_base + 3], a3); atomicAdd(&s_sq[k_base + 3], q3);
        }
    }

    // Head diagonals k < k_start (at most 3): lane-parallel over rows.
    if (w < k_start) {
        const int h  = w;
        const int Lh = 511 - h;
        float hs = 0.f, hq = 0.f;
        for (int p = s + 8 * lane; p < Lh; p += 256) {
            const float x = __ldg(base + (size_t)513 * p + (h + 1));
            hs += x; hq = fmaf(x, x, hq);
        }
        #pragma unroll
        for (int o = 16; o > 0; o >>= 1) {
            hs += __shfl_down_sync(0xFFFFFFFFu, hs, o);
            hq += __shfl_down_sync(0xFFFFFFFFu, hq, o);
        }
        if (lane == 0) { atomicAdd(&s_sum[h], hs); atomicAdd(&s_sq[h], hq); }
    }
    __syncthreads();

    for (int i = tid; i < KP; i += 128) {
        g_psum[s][b][i] = s_sum[i];
        g_psq [s][b][i] = s_sq [i];
    }
}

__global__ __launch_bounds__(512)
void finalize_kernel(float* __restrict__ out, int out_size) {
    __shared__ float red[512];
    const int b = blockIdx.x;
    const int k = threadIdx.x;

    float scaled = 0.0f;
    if (k < 510) {
        float su = 0.f, sq = 0.f;
        #pragma unroll
        for (int s = 0; s < S; ++s) {
            su += g_psum[s][b][k];
            sq += g_psq [s][b][k];
        }
        const float Lf   = (float)(511 - k);
        const float mean = su / Lf;
        float var = (sq - su * mean) / (Lf - 1.0f);
        var = fmaxf(var, 0.0f);
        scaled = sqrtf(var) * Lf * 0.2f;
    }
    red[k] = scaled;
    __syncthreads();

    #pragma unroll
    for (int st = 256; st >= 1; st >>= 1) {
        if (k < st) red[k] += red[k + st];
        __syncthreads();
    }

    if (k == 0) {
        const float loss = red[0] * (1.0f / 510.0f);
        out[b] = loss;
        if (out_size >= 256) out[128 + b] = loss;
    }
}

extern "C" void kernel_launch(void* const* d_in, const int* in_sizes, int n_in,
                              void* d_out, int out_size) {
    const float* ssmap = (const float*)d_in[0];
    float* out = (float*)d_out;
    accum_kernel<<<dim3(BATCH, S), 128>>>(ssmap);
    finalize_kernel<<<BATCH, 512>>>(out, out_size);
}